// round 15
// baseline (speedup 1.0000x reference)
#include <cuda_runtime.h>
#include <float.h>
#include <math.h>
#include <stdint.h>

#define C_ 32
#define D_ 48
#define H_ 64
#define W_ 128
#define HW 8192
#define CDHW 12582912
#define GDIR 1310720

__device__ float g_xT[CDHW];
__device__ float g_kT[2 * GDIR];
__device__ float g_aggH0[CDHW];
__device__ float g_aggH1[CDHW];
__device__ float g_aggT0[CDHW];
__device__ float g_aggT1[CDHW];
__device__ float g_y[CDHW];          // relu(bn1(max4)), tf32-pre-rounded
__device__ float g_wfA[27648];       // A fragments: [tap][kw][ks][mt][lane][reg] (3072 f / tap)

__device__ __forceinline__ float to_tf32(float x) {
    float r; asm("cvt.rna.tf32.f32 %0, %1;" : "=f"(r) : "f"(x)); return r;
}
__device__ __forceinline__ void cpa16(uint32_t dst, const void* src) {
    asm volatile("cp.async.ca.shared.global [%0], [%1], 16;" :: "r"(dst), "l"(src) : "memory");
}
#define CPA_COMMIT() asm volatile("cp.async.commit_group;" ::: "memory")
#define CPA_WAIT(n)  asm volatile("cp.async.wait_group %0;" :: "n"(n) : "memory")

// ===================== prep: tiled transposes (scans) ======================
__global__ void __launch_bounds__(256) prep_transpose(const float* __restrict__ x,
                                                      const float* __restrict__ g)
{
    __shared__ float tile[32][33];
    const int b = blockIdx.x;
    const float* src;
    float* dst;
    if (b < 12288) {
        const int plane = b >> 3;
        src = x + plane * HW; dst = g_xT + plane * HW;
    } else {
        const int kplane = (b - 12288) >> 3;
        const int dir = kplane / 160;
        const int rest = kplane - dir * 160;
        src = g + dir * GDIR + rest * HW; dst = g_kT + kplane * HW;
    }
    const int tile_id = b & 7;
    const int h0 = (tile_id >> 2) * 32, w0 = (tile_id & 3) * 32;
    const int tx = threadIdx.x & 31, ty = threadIdx.x >> 5;
#pragma unroll
    for (int j = 0; j < 4; ++j) { const int r = ty + j * 8; tile[r][tx] = src[(h0 + r) * W_ + w0 + tx]; }
    __syncthreads();
#pragma unroll
    for (int j = 0; j < 4; ++j) { const int r = ty + j * 8; dst[(w0 + r) * H_ + h0 + tx] = tile[tx][r]; }
}

// weights -> mma A-fragment order, tf32 rounded.
__global__ void __launch_bounds__(256) prep_wfrag(const float* __restrict__ wr)
{
    const int i = blockIdx.x * 256 + threadIdx.x;
    if (i >= 27648) return;
    const int reg = i & 3;
    const int lane = (i >> 2) & 31;
    const int mt = (i >> 7) & 1;
    const int ks = (i >> 8) & 3;
    const int kwtap = i >> 10;                 // tap*3+kw
    const int m = mt * 16 + (lane >> 2) + ((reg & 1) ? 8 : 0);   // co
    const int k = ks * 8 + (lane & 3) + ((reg & 2) ? 4 : 0);     // ci
    g_wfA[i] = to_tf32(wr[(m * C_ + k) * 27 + kwtap]);
}

// ===================== register-fiber SGA scan =============================
__device__ __forceinline__ void pf48(const float* __restrict__ xp, const float* __restrict__ kp,
                                     int off, float X[48], float K[5])
{
#pragma unroll
    for (int d = 0; d < 48; ++d) X[d] = __ldg(xp + d * HW + off);
#pragma unroll
    for (int i = 0; i < 5; ++i)  K[i] = __ldg(kp + i * HW + off);
}
__device__ __forceinline__ void sga_body(float A[48], const float X[48], const float K[5],
                                         float* __restrict__ op, int off)
{
    const float s = fabsf(K[0]) + fabsf(K[1]) + fabsf(K[2]) + fabsf(K[3]) + fabsf(K[4]);
    const float inv = __fdividef(1.0f, fmaxf(s, 1e-12f));
    const float w0 = K[0]*inv, w1 = K[1]*inv, w2 = K[2]*inv, w3 = K[3]*inv, w4 = K[4]*inv;
    float t[24];
#pragma unroll
    for (int i = 0; i < 24; ++i) t[i] = fmaxf(A[2*i], A[2*i+1]);
#pragma unroll
    for (int i = 0; i < 12; ++i) t[i] = fmaxf(t[2*i], t[2*i+1]);
#pragma unroll
    for (int i = 0; i < 6; ++i)  t[i] = fmaxf(t[2*i], t[2*i+1]);
    const float m = fmaxf(fmaxf(fmaxf(t[0],t[1]),fmaxf(t[2],t[3])),fmaxf(t[4],t[5]));
    float pm = 0.0f;
#pragma unroll
    for (int d = 0; d < 48; ++d) {
        const float nxt = (d < 47) ? A[d+1] : 0.0f;
        float v = w0 * X[d];
        v = fmaf(w1, A[d], v); v = fmaf(w2, pm, v); v = fmaf(w3, nxt, v); v = fmaf(w4, m, v);
        pm = A[d]; A[d] = v; op[d * HW + off] = v;
    }
}
__device__ __forceinline__ void scan_warp(const float* __restrict__ xb, const float* __restrict__ kb,
                                          float* __restrict__ ob, int maj, int mn, int rev, int gw, int lane)
{
    const int wpc = mn >> 5;
    const int c = gw / wpc;
    const int m = (gw - c * wpc) * 32 + lane;
    const float* xp = xb + c * 48 * HW + m;
    float* op = ob + c * 48 * HW + m;
    const float* kp = kb + c * 5 * HW + m;
    const int ds = rev ? -mn : mn;
    int off = rev ? (maj - 1) * mn : 0;
    float A[48];
#pragma unroll
    for (int d = 0; d < 48; ++d) { const float v = __ldg(xp + d * HW + off); A[d] = v; op[d * HW + off] = v; }
    float X0[48], K0[5], X1[48], K1[5];
    int offc = off + ds;
    pf48(xp, kp, offc, X0, K0);
    const int nst = maj - 1;
    for (int s = 0; s < nst; s += 2) {
        const int offn = offc + ds;
        if (s + 1 < nst) pf48(xp, kp, offn, X1, K1);
        sga_body(A, X0, K0, op, offc);
        if (s + 1 < nst) {
            const int offn2 = offn + ds;
            if (s + 2 < nst) pf48(xp, kp, offn2, X0, K0);
            sga_body(A, X1, K1, op, offn);
            offc = offn2;
        }
    }
}
__global__ void __launch_bounds__(128) scan_kernel(const float* __restrict__ x, const float* __restrict__ g)
{
    const int blk = blockIdx.x, warp = threadIdx.x >> 5, lane = threadIdx.x & 31;
    if (blk < 32)       scan_warp(x, g + 2*GDIR, g_aggH0, H_, W_, 0, blk*4 + warp, lane);
    else if (blk < 64)  scan_warp(x, g + 3*GDIR, g_aggH1, H_, W_, 1, (blk-32)*4 + warp, lane);
    else if (blk < 80)  scan_warp(g_xT, g_kT,        g_aggT0, W_, H_, 0, (blk-64)*4 + warp, lane);
    else                scan_warp(g_xT, g_kT + GDIR, g_aggT1, W_, H_, 1, (blk-80)*4 + warp, lane);
}

// ===================== combine: max4 + BN1 + ReLU (-> tf32) ================
__global__ void __launch_bounds__(256) combine_kernel(const float* __restrict__ s1, const float* __restrict__ b1)
{
    __shared__ float t0[32][33], t1[32][33];
    const int b = blockIdx.x;
    const int plane = b >> 3, tile_id = b & 7;
    const int h0 = (tile_id >> 2) * 32, w0 = (tile_id & 3) * 32;
    const int c = plane / 48;
    const int tx = threadIdx.x & 31, ty = threadIdx.x >> 5;
    const int pb = plane * HW;
#pragma unroll
    for (int j = 0; j < 4; ++j) {
        const int r = ty + j * 8;
        const int ta = pb + (w0 + r) * H_ + h0 + tx;
        t0[r][tx] = g_aggT0[ta]; t1[r][tx] = g_aggT1[ta];
    }
    __syncthreads();
    const float inv1 = s1[c] * rsqrtf(1.0f + 1e-5f);
    const float bb = b1[c];
#pragma unroll
    for (int j = 0; j < 4; ++j) {
        const int hh = ty + j * 8;
        const int na = pb + (h0 + hh) * W_ + w0 + tx;
        float v = fmaxf(fmaxf(g_aggH0[na], g_aggH1[na]), fmaxf(t0[tx][hh], t1[tx][hh]));
        g_y[na] = to_tf32(fmaxf(v * inv1 + bb, 0.0f));
    }
}

// ============ mma.sync tf32 conv + BN2 + residual + ReLU ===================
// Block = (d, h-pair). 256 threads: warp = r*4 + wq (r = output row 0/1).
#define MMA_TF32(d0,d1,d2,d3, a0,a1,a2,a3, b0,b1)                               \
    asm volatile("mma.sync.aligned.m16n8k8.row.col.f32.tf32.tf32.f32 "          \
        "{%0,%1,%2,%3}, {%4,%5,%6,%7}, {%8,%9}, {%0,%1,%2,%3};"                 \
        : "+f"(d0), "+f"(d1), "+f"(d2), "+f"(d3)                                 \
        : "r"(a0), "r"(a1), "r"(a2), "r"(a3), "r"(b0), "r"(b1))

#define CONV_SMEM (27648 * 4 + 3 * 32 * 136 * 4)

__global__ void __launch_bounds__(256, 1) conv_mma(const float* __restrict__ x,
                                                   const float* __restrict__ s2,
                                                   const float* __restrict__ b2,
                                                   float* __restrict__ out)
{
    extern __shared__ float sm[];
    float* wsh = sm;                                  // 27648 floats (9 taps x 3072)
    float* insh = sm + 27648;                         // 3 x 32 x 136

    const int d = blockIdx.x >> 5;
    const int h2 = (blockIdx.x & 31) * 2;
    const int t = threadIdx.x;
    const int lane = t & 31;
    const int warp = t >> 5;
    const int r = warp >> 2;                          // output row in pair
    const int wq = warp & 3;                          // w quarter
    const int lt = lane & 3, lg = lane >> 2;
    const int h = h2 + r;

    const uint32_t insh_s = (uint32_t)__cvta_generic_to_shared(insh);

    // prefetch stage 0 input via cp.async
    {
        const int zd = d - 1, zh = h2 - 1;
        if (zd >= 0 && zh >= 0) {
#pragma unroll
            for (int k = 0; k < 4; ++k) {
                const int j = t + k * 256;
                const int ci = j >> 5, q = j & 31;
                cpa16(insh_s + (ci * 136 + 4 + q * 4) * 4,
                      g_y + ((ci * D_ + zd) * H_ + zh) * W_ + q * 4);
            }
        }
        CPA_COMMIT();
    }

    // preload all 9 taps' A-fragments (one-time)
#pragma unroll
    for (int k = 0; k < 27; ++k)
        ((float4*)wsh)[k * 256 + t] = ((const float4*)g_wfA)[k * 256 + t];

    // zero guard columns of all 3 ring buffers
    if (t < 96) {
        const int b = t >> 5, ci = t & 31;
        insh[b * 4352 + ci * 136 + 3] = 0.0f;
        insh[b * 4352 + ci * 136 + 132] = 0.0f;
    }

    float dacc[2][4][4];
#pragma unroll
    for (int a = 0; a < 2; ++a)
#pragma unroll
        for (int b = 0; b < 4; ++b)
#pragma unroll
            for (int q = 0; q < 4; ++q) dacc[a][b][q] = 0.0f;

#pragma unroll 1
    for (int s = 0; s < 12; ++s) {
        const int sd = s % 3, sz = s / 3;
        // prefetch stage s+1 into ring slot (s+1)%3
        if (s < 11) {
            const int sn = s + 1;
            const int zd = d - 1 + sn % 3, zh = h2 - 1 + sn / 3;
            if (zd >= 0 && zd < D_ && zh >= 0 && zh < H_) {
                const uint32_t buf_s = insh_s + (sn % 3) * 4352 * 4;
#pragma unroll
                for (int k = 0; k < 4; ++k) {
                    const int j = t + k * 256;
                    const int ci = j >> 5, q = j & 31;
                    cpa16(buf_s + (ci * 136 + 4 + q * 4) * 4,
                          g_y + ((ci * D_ + zd) * H_ + zh) * W_ + q * 4);
                }
            }
            CPA_COMMIT();
            CPA_WAIT(1);
        } else {
            CPA_WAIT(0);
        }
        __syncthreads();

        const int zd = d - 1 + sd, zh = h2 - 1 + sz;
        if (zd < 0 || zd >= D_ || zh < 0 || zh >= H_) continue;
        const int kh = sz - r;
        if (kh < 0 || kh > 2) continue;

        const float* buf = insh + (s % 3) * 4352;
        const float* wb = wsh + (sd * 3 + kh) * 3072;   // FIXED: tap stride = 3072
#pragma unroll
        for (int kw = 0; kw < 3; ++kw) {
            const int wbase = 4 + wq * 32 + lg + kw - 1;
#pragma unroll
            for (int ks = 0; ks < 4; ++ks) {
                const float4 af0 = *(const float4*)&wb[((kw * 4 + ks) * 2 + 0) * 128 + lane * 4];
                const float4 af1 = *(const float4*)&wb[((kw * 4 + ks) * 2 + 1) * 128 + lane * 4];
                const uint32_t a00 = __float_as_uint(af0.x), a01 = __float_as_uint(af0.y),
                               a02 = __float_as_uint(af0.z), a03 = __float_as_uint(af0.w);
                const uint32_t a10 = __float_as_uint(af1.x), a11 = __float_as_uint(af1.y),
                               a12 = __float_as_uint(af1.z), a13 = __float_as_uint(af1.w);
                const int k0 = ks * 8 + lt;
#pragma unroll
                for (int nt = 0; nt < 4; ++nt) {
                    const uint32_t b0 = __float_as_uint(buf[k0 * 136 + wbase + nt * 8]);
                    const uint32_t b1 = __float_as_uint(buf[(k0 + 4) * 136 + wbase + nt * 8]);
                    MMA_TF32(dacc[0][nt][0], dacc[0][nt][1], dacc[0][nt][2], dacc[0][nt][3],
                             a00, a01, a02, a03, b0, b1);
                    MMA_TF32(dacc[1][nt][0], dacc[1][nt][1], dacc[1][nt][2], dacc[1][nt][3],
                             a10, a11, a12, a13, b0, b1);
                }
            }
        }
    }

    // epilogue: BN2 + residual + ReLU
    const float rsq = rsqrtf(1.0f + 1e-5f);
#pragma unroll
    for (int mt = 0; mt < 2; ++mt) {
#pragma unroll
        for (int rr = 0; rr < 2; ++rr) {
            const int co = mt * 16 + lg + rr * 8;
            const float inv = s2[co] * rsq, bb = b2[co];
            const int rowbase = ((co * D_ + d) * H_ + h) * W_ + wq * 32 + 2 * lt;
#pragma unroll
            for (int nt = 0; nt < 4; ++nt) {
                const int idx = rowbase + nt * 8;
                const float2 xv = *(const float2*)(x + idx);
                float2 ov;
                ov.x = fmaxf(dacc[mt][nt][rr * 2 + 0] * inv + bb + xv.x, 0.0f);
                ov.y = fmaxf(dacc[mt][nt][rr * 2 + 1] * inv + bb + xv.y, 0.0f);
                *(float2*)(out + idx) = ov;
            }
        }
    }
}

// ===========================================================================
extern "C" void kernel_launch(void* const* d_in, const int* in_sizes, int n_in,
                              void* d_out, int out_size)
{
    const float* x  = (const float*)d_in[0];
    const float* g  = (const float*)d_in[1];
    const float* wr = (const float*)d_in[2];
    const float* s1 = (const float*)d_in[3];
    const float* b1 = (const float*)d_in[4];
    const float* s2 = (const float*)d_in[5];
    const float* b2 = (const float*)d_in[6];
    float* out = (float*)d_out;

    cudaFuncSetAttribute(conv_mma, cudaFuncAttributeMaxDynamicSharedMemorySize, CONV_SMEM);

    prep_transpose<<<14848, 256>>>(x, g);
    prep_wfrag<<<108, 256>>>(wr);
    scan_kernel<<<96, 128>>>(x, g);
    combine_kernel<<<12288, 256>>>(s1, b1);
    conv_mma<<<1536, 256, CONV_SMEM>>>(x, s2, b2, out);
}

// round 16
// speedup vs baseline: 1.0319x; 1.0319x over previous
#include <cuda_runtime.h>
#include <float.h>
#include <math.h>
#include <stdint.h>

#define C_ 32
#define D_ 48
#define H_ 64
#define W_ 128
#define HW 8192
#define CDHW 12582912
#define GDIR 1310720

__device__ float g_xT[CDHW];
__device__ float g_kT[2 * GDIR];
__device__ float g_aggH0[CDHW];
__device__ float g_aggH1[CDHW];
__device__ float g_aggT0[CDHW];
__device__ float g_aggT1[CDHW];
__device__ float g_y[CDHW];          // relu(bn1(max4)), tf32-pre-rounded
__device__ float g_wfA[27648];       // A fragments: [tap][kw][ks][mt][lane][reg] (3072 f / tap)

__device__ __forceinline__ float to_tf32(float x) {
    float r; asm("cvt.rna.tf32.f32 %0, %1;" : "=f"(r) : "f"(x)); return r;
}
__device__ __forceinline__ void cpa16(uint32_t dst, const void* src) {
    asm volatile("cp.async.ca.shared.global [%0], [%1], 16;" :: "r"(dst), "l"(src) : "memory");
}
#define CPA_COMMIT() asm volatile("cp.async.commit_group;" ::: "memory")
#define CPA_WAIT(n)  asm volatile("cp.async.wait_group %0;" :: "n"(n) : "memory")

// ===================== prep: tiled transposes (scans) ======================
__global__ void __launch_bounds__(256) prep_transpose(const float* __restrict__ x,
                                                      const float* __restrict__ g)
{
    __shared__ float tile[32][33];
    const int b = blockIdx.x;
    const float* src;
    float* dst;
    if (b < 12288) {
        const int plane = b >> 3;
        src = x + plane * HW; dst = g_xT + plane * HW;
    } else {
        const int kplane = (b - 12288) >> 3;
        const int dir = kplane / 160;
        const int rest = kplane - dir * 160;
        src = g + dir * GDIR + rest * HW; dst = g_kT + kplane * HW;
    }
    const int tile_id = b & 7;
    const int h0 = (tile_id >> 2) * 32, w0 = (tile_id & 3) * 32;
    const int tx = threadIdx.x & 31, ty = threadIdx.x >> 5;
#pragma unroll
    for (int j = 0; j < 4; ++j) { const int r = ty + j * 8; tile[r][tx] = src[(h0 + r) * W_ + w0 + tx]; }
    __syncthreads();
#pragma unroll
    for (int j = 0; j < 4; ++j) { const int r = ty + j * 8; dst[(w0 + r) * H_ + h0 + tx] = tile[tx][r]; }
}

// weights -> mma A-fragment order, tf32 rounded.
__global__ void __launch_bounds__(256) prep_wfrag(const float* __restrict__ wr)
{
    const int i = blockIdx.x * 256 + threadIdx.x;
    if (i >= 27648) return;
    const int reg = i & 3;
    const int lane = (i >> 2) & 31;
    const int mt = (i >> 7) & 1;
    const int ks = (i >> 8) & 3;
    const int kwtap = i >> 10;                 // tap*3+kw
    const int m = mt * 16 + (lane >> 2) + ((reg & 1) ? 8 : 0);   // co
    const int k = ks * 8 + (lane & 3) + ((reg & 2) ? 4 : 0);     // ci
    g_wfA[i] = to_tf32(wr[(m * C_ + k) * 27 + kwtap]);
}

// ===================== register-fiber SGA scan =============================
__device__ __forceinline__ void pf48(const float* __restrict__ xp, const float* __restrict__ kp,
                                     int off, float X[48], float K[5])
{
#pragma unroll
    for (int d = 0; d < 48; ++d) X[d] = __ldg(xp + d * HW + off);
#pragma unroll
    for (int i = 0; i < 5; ++i)  K[i] = __ldg(kp + i * HW + off);
}
__device__ __forceinline__ void sga_body(float A[48], const float X[48], const float K[5],
                                         float* __restrict__ op, int off)
{
    const float s = fabsf(K[0]) + fabsf(K[1]) + fabsf(K[2]) + fabsf(K[3]) + fabsf(K[4]);
    const float inv = __fdividef(1.0f, fmaxf(s, 1e-12f));
    const float w0 = K[0]*inv, w1 = K[1]*inv, w2 = K[2]*inv, w3 = K[3]*inv, w4 = K[4]*inv;
    float t[24];
#pragma unroll
    for (int i = 0; i < 24; ++i) t[i] = fmaxf(A[2*i], A[2*i+1]);
#pragma unroll
    for (int i = 0; i < 12; ++i) t[i] = fmaxf(t[2*i], t[2*i+1]);
#pragma unroll
    for (int i = 0; i < 6; ++i)  t[i] = fmaxf(t[2*i], t[2*i+1]);
    const float m = fmaxf(fmaxf(fmaxf(t[0],t[1]),fmaxf(t[2],t[3])),fmaxf(t[4],t[5]));
    float pm = 0.0f;
#pragma unroll
    for (int d = 0; d < 48; ++d) {
        const float nxt = (d < 47) ? A[d+1] : 0.0f;
        float v = w0 * X[d];
        v = fmaf(w1, A[d], v); v = fmaf(w2, pm, v); v = fmaf(w3, nxt, v); v = fmaf(w4, m, v);
        pm = A[d]; A[d] = v; op[d * HW + off] = v;
    }
}
__device__ __forceinline__ void scan_warp(const float* __restrict__ xb, const float* __restrict__ kb,
                                          float* __restrict__ ob, int maj, int mn, int rev, int gw, int lane)
{
    const int wpc = mn >> 5;
    const int c = gw / wpc;
    const int m = (gw - c * wpc) * 32 + lane;
    const float* xp = xb + c * 48 * HW + m;
    float* op = ob + c * 48 * HW + m;
    const float* kp = kb + c * 5 * HW + m;
    const int ds = rev ? -mn : mn;
    int off = rev ? (maj - 1) * mn : 0;
    float A[48];
#pragma unroll
    for (int d = 0; d < 48; ++d) { const float v = __ldg(xp + d * HW + off); A[d] = v; op[d * HW + off] = v; }
    float X0[48], K0[5], X1[48], K1[5];
    int offc = off + ds;
    pf48(xp, kp, offc, X0, K0);
    const int nst = maj - 1;
    for (int s = 0; s < nst; s += 2) {
        const int offn = offc + ds;
        if (s + 1 < nst) pf48(xp, kp, offn, X1, K1);
        sga_body(A, X0, K0, op, offc);
        if (s + 1 < nst) {
            const int offn2 = offn + ds;
            if (s + 2 < nst) pf48(xp, kp, offn2, X0, K0);
            sga_body(A, X1, K1, op, offn);
            offc = offn2;
        }
    }
}
__global__ void __launch_bounds__(128) scan_kernel(const float* __restrict__ x, const float* __restrict__ g)
{
    const int blk = blockIdx.x, warp = threadIdx.x >> 5, lane = threadIdx.x & 31;
    if (blk < 32)       scan_warp(x, g + 2*GDIR, g_aggH0, H_, W_, 0, blk*4 + warp, lane);
    else if (blk < 64)  scan_warp(x, g + 3*GDIR, g_aggH1, H_, W_, 1, (blk-32)*4 + warp, lane);
    else if (blk < 80)  scan_warp(g_xT, g_kT,        g_aggT0, W_, H_, 0, (blk-64)*4 + warp, lane);
    else                scan_warp(g_xT, g_kT + GDIR, g_aggT1, W_, H_, 1, (blk-80)*4 + warp, lane);
}

// ===================== combine: max4 + BN1 + ReLU (-> tf32) ================
__global__ void __launch_bounds__(256) combine_kernel(const float* __restrict__ s1, const float* __restrict__ b1)
{
    __shared__ float t0[32][33], t1[32][33];
    const int b = blockIdx.x;
    const int plane = b >> 3, tile_id = b & 7;
    const int h0 = (tile_id >> 2) * 32, w0 = (tile_id & 3) * 32;
    const int c = plane / 48;
    const int tx = threadIdx.x & 31, ty = threadIdx.x >> 5;
    const int pb = plane * HW;
#pragma unroll
    for (int j = 0; j < 4; ++j) {
        const int r = ty + j * 8;
        const int ta = pb + (w0 + r) * H_ + h0 + tx;
        t0[r][tx] = g_aggT0[ta]; t1[r][tx] = g_aggT1[ta];
    }
    __syncthreads();
    const float inv1 = s1[c] * rsqrtf(1.0f + 1e-5f);
    const float bb = b1[c];
#pragma unroll
    for (int j = 0; j < 4; ++j) {
        const int hh = ty + j * 8;
        const int na = pb + (h0 + hh) * W_ + w0 + tx;
        float v = fmaxf(fmaxf(g_aggH0[na], g_aggH1[na]), fmaxf(t0[tx][hh], t1[tx][hh]));
        g_y[na] = to_tf32(fmaxf(v * inv1 + bb, 0.0f));
    }
}

// ============ mma.sync tf32 conv + BN2 + residual + ReLU ===================
// Persistent blocks (grid=152, 1/SM, 512 threads). Tile = (d, 4 h-rows).
// 16 warps: warp = r*4 + wq (r = row 0..3, wq = w quarter).
// smem: all 9 taps' A fragments (27648 f) + 4-slot input ring (4 x 32 x 136).
#define MMA_TF32(d0,d1,d2,d3, a0,a1,a2,a3, b0,b1)                               \
    asm volatile("mma.sync.aligned.m16n8k8.row.col.f32.tf32.tf32.f32 "          \
        "{%0,%1,%2,%3}, {%4,%5,%6,%7}, {%8,%9}, {%0,%1,%2,%3};"                 \
        : "+f"(d0), "+f"(d1), "+f"(d2), "+f"(d3)                                 \
        : "r"(a0), "r"(a1), "r"(a2), "r"(a3), "r"(b0), "r"(b1))

#define NTILES 768                       // 48 d x 16 h-quads
#define NSTG 18                          // 6 zh x 3 kd per tile
#define CONV_SMEM (27648 * 4 + 4 * 4352 * 4)

__global__ void __launch_bounds__(512, 1) conv_mma(const float* __restrict__ x,
                                                   const float* __restrict__ s2,
                                                   const float* __restrict__ b2,
                                                   float* __restrict__ out)
{
    extern __shared__ float sm[];
    float* wsh = sm;                                  // 27648 floats (9 taps x 3072)
    float* insh = sm + 27648;                         // 4 x 4352

    const int t = threadIdx.x;
    const int lane = t & 31;
    const int warp = t >> 5;
    const int r = warp >> 2;                          // output row in quad (0..3)
    const int wq = warp & 3;                          // w quarter
    const int lt = lane & 3, lg = lane >> 2;

    const uint32_t insh_s = (uint32_t)__cvta_generic_to_shared(insh);

    // one-time: preload all 9 taps' A-fragments (6912 float4, 512 threads)
#pragma unroll
    for (int k = 0; k < 14; ++k) {
        const int j = k * 512 + t;
        if (j < 6912) ((float4*)wsh)[j] = ((const float4*)g_wfA)[j];
    }
    // one-time: zero guard columns of the 4 ring slots
    if (t < 128) {
        const int b = t >> 5, ci = t & 31;
        insh[b * 4352 + ci * 136 + 3] = 0.0f;
        insh[b * 4352 + ci * 136 + 132] = 0.0f;
    }
    __syncthreads();

    for (int tile = blockIdx.x; tile < NTILES; tile += gridDim.x) {
        const int d = tile >> 4;
        const int h4 = (tile & 15) * 4;
        const int h = h4 + r;

        // issue prefetch for stages 0 and 1 (one commit each)
#pragma unroll
        for (int s0 = 0; s0 < 2; ++s0) {
            const int zd = d - 1 + s0 % 3, zh = h4 - 1 + s0 / 3;
            if (zd >= 0 && zd < D_ && zh >= 0 && zh < H_) {
                const uint32_t buf_s = insh_s + (s0 & 3) * 4352 * 4;
#pragma unroll
                for (int k = 0; k < 2; ++k) {
                    const int j = t + k * 512;
                    const int ci = j >> 5, q = j & 31;
                    cpa16(buf_s + (ci * 136 + 4 + q * 4) * 4,
                          g_y + ((ci * D_ + zd) * H_ + zh) * W_ + q * 4);
                }
            }
            CPA_COMMIT();
        }

        float dacc[2][4][4];
#pragma unroll
        for (int a = 0; a < 2; ++a)
#pragma unroll
            for (int b = 0; b < 4; ++b)
#pragma unroll
                for (int q = 0; q < 4; ++q) dacc[a][b][q] = 0.0f;

#pragma unroll 1
        for (int s = 0; s < NSTG; ++s) {
            // prefetch stage s+2
            if (s + 2 < NSTG) {
                const int sn = s + 2;
                const int zd = d - 1 + sn % 3, zh = h4 - 1 + sn / 3;
                if (zd >= 0 && zd < D_ && zh >= 0 && zh < H_) {
                    const uint32_t buf_s = insh_s + (sn & 3) * 4352 * 4;
#pragma unroll
                    for (int k = 0; k < 2; ++k) {
                        const int j = t + k * 512;
                        const int ci = j >> 5, q = j & 31;
                        cpa16(buf_s + (ci * 136 + 4 + q * 4) * 4,
                              g_y + ((ci * D_ + zd) * H_ + zh) * W_ + q * 4);
                    }
                }
            }
            CPA_COMMIT();
            CPA_WAIT(2);
            __syncthreads();

            const int sd = s % 3, sz = s / 3;
            const int zd = d - 1 + sd, zh = h4 - 1 + sz;
            if (zd < 0 || zd >= D_ || zh < 0 || zh >= H_) continue;
            const int kh = sz - r;
            if (kh < 0 || kh > 2) continue;

            const float* buf = insh + (s & 3) * 4352;
            const float* wb = wsh + (sd * 3 + kh) * 3072;
#pragma unroll
            for (int kw = 0; kw < 3; ++kw) {
                const int wbase = 4 + wq * 32 + lg + kw - 1;
#pragma unroll
                for (int ks = 0; ks < 4; ++ks) {
                    const float4 af0 = *(const float4*)&wb[((kw * 4 + ks) * 2 + 0) * 128 + lane * 4];
                    const float4 af1 = *(const float4*)&wb[((kw * 4 + ks) * 2 + 1) * 128 + lane * 4];
                    const uint32_t a00 = __float_as_uint(af0.x), a01 = __float_as_uint(af0.y),
                                   a02 = __float_as_uint(af0.z), a03 = __float_as_uint(af0.w);
                    const uint32_t a10 = __float_as_uint(af1.x), a11 = __float_as_uint(af1.y),
                                   a12 = __float_as_uint(af1.z), a13 = __float_as_uint(af1.w);
                    const int k0 = ks * 8 + lt;
#pragma unroll
                    for (int nt = 0; nt < 4; ++nt) {
                        const uint32_t b0 = __float_as_uint(buf[k0 * 136 + wbase + nt * 8]);
                        const uint32_t b1 = __float_as_uint(buf[(k0 + 4) * 136 + wbase + nt * 8]);
                        MMA_TF32(dacc[0][nt][0], dacc[0][nt][1], dacc[0][nt][2], dacc[0][nt][3],
                                 a00, a01, a02, a03, b0, b1);
                        MMA_TF32(dacc[1][nt][0], dacc[1][nt][1], dacc[1][nt][2], dacc[1][nt][3],
                                 a10, a11, a12, a13, b0, b1);
                    }
                }
            }
        }

        // epilogue: BN2 + residual + ReLU
        const float rsq = rsqrtf(1.0f + 1e-5f);
#pragma unroll
        for (int mt = 0; mt < 2; ++mt) {
#pragma unroll
            for (int rr = 0; rr < 2; ++rr) {
                const int co = mt * 16 + lg + rr * 8;
                const float inv = s2[co] * rsq, bb = b2[co];
                const int rowbase = ((co * D_ + d) * H_ + h) * W_ + wq * 32 + 2 * lt;
#pragma unroll
                for (int nt = 0; nt < 4; ++nt) {
                    const int idx = rowbase + nt * 8;
                    const float2 xv = *(const float2*)(x + idx);
                    float2 ov;
                    ov.x = fmaxf(dacc[mt][nt][rr * 2 + 0] * inv + bb + xv.x, 0.0f);
                    ov.y = fmaxf(dacc[mt][nt][rr * 2 + 1] * inv + bb + xv.y, 0.0f);
                    *(float2*)(out + idx) = ov;
                }
            }
        }
        __syncthreads();   // protect ring slots before next tile's prefetch
    }
}

// ===========================================================================
extern "C" void kernel_launch(void* const* d_in, const int* in_sizes, int n_in,
                              void* d_out, int out_size)
{
    const float* x  = (const float*)d_in[0];
    const float* g  = (const float*)d_in[1];
    const float* wr = (const float*)d_in[2];
    const float* s1 = (const float*)d_in[3];
    const float* b1 = (const float*)d_in[4];
    const float* s2 = (const float*)d_in[5];
    const float* b2 = (const float*)d_in[6];
    float* out = (float*)d_out;

    cudaFuncSetAttribute(conv_mma, cudaFuncAttributeMaxDynamicSharedMemorySize, CONV_SMEM);

    prep_transpose<<<14848, 256>>>(x, g);
    prep_wfrag<<<108, 256>>>(wr);
    scan_kernel<<<96, 128>>>(x, g);
    combine_kernel<<<12288, 256>>>(s1, b1);
    conv_mma<<<152, 512, CONV_SMEM>>>(x, s2, b2, out);
}